// round 10
// baseline (speedup 1.0000x reference)
#include <cuda_runtime.h>
#include <cuda_fp16.h>
#include <stdint.h>
#include <math.h>

#define BB 64
#define LL 196
#define DD 2048
#define II 512
#define MM (BB * LL)   // 12544

typedef __half f16;

// ---------------- device scratch (allocation-free) ----------------
__device__ f16 g_fv_h[(size_t)MM * DD];
__device__ f16 g_fvs_h[(size_t)MM * II];
__device__ f16 g_WfT_h[(size_t)II * DD];   // [I, D] K-major
__device__ f16 g_WaT_h[(size_t)DD * II];   // [D, I] K-major
__device__ float g_hs[BB * II];

// ---------------- helpers ----------------
__device__ __forceinline__ uint32_t smem_u32(const void* p) {
    uint32_t a;
    asm("{ .reg .u64 t; cvta.to.shared.u64 t, %1; cvt.u32.u64 %0, t; }"
        : "=r"(a) : "l"(p));
    return a;
}
__device__ __forceinline__ void cp_async16(uint32_t s, const void* g) {
    asm volatile("cp.async.cg.shared.global [%0], [%1], 16;" :: "r"(s), "l"(g));
}
__device__ __forceinline__ void cp_commit() {
    asm volatile("cp.async.commit_group;" ::: "memory");
}
__device__ __forceinline__ void cp_wait2() {
    asm volatile("cp.async.wait_group 2;" ::: "memory");
}
__device__ __forceinline__ void cp_wait0() {
    asm volatile("cp.async.wait_group 0;" ::: "memory");
}
__device__ __forceinline__ void ldsm4(uint32_t& r0, uint32_t& r1, uint32_t& r2,
                                      uint32_t& r3, uint32_t addr) {
    asm volatile("ldmatrix.sync.aligned.m8n8.x4.shared.b16 {%0,%1,%2,%3}, [%4];"
                 : "=r"(r0), "=r"(r1), "=r"(r2), "=r"(r3) : "r"(addr));
}
__device__ __forceinline__ void mma16816(float* c, const uint32_t* a,
                                         const uint32_t* b) {
    asm volatile(
        "mma.sync.aligned.m16n8k16.row.col.f32.f16.f16.f32 "
        "{%0,%1,%2,%3}, {%4,%5,%6,%7}, {%8,%9}, {%0,%1,%2,%3};"
        : "+f"(c[0]), "+f"(c[1]), "+f"(c[2]), "+f"(c[3])
        : "r"(a[0]), "r"(a[1]), "r"(a[2]), "r"(a[3]), "r"(b[0]), "r"(b[1]));
}

// ---------------- conversion kernels ----------------
// fv -> fp16
__global__ void conv_fv_kernel(const float* __restrict__ in) {
    size_t i = (size_t)blockIdx.x * blockDim.x + threadIdx.x;   // MM*DD/4
    float4 v = ((const float4*)in)[i];
    __half2 a = __floats2half2_rn(v.x, v.y);
    __half2 b = __floats2half2_rn(v.z, v.w);
    ((__half2*)g_fv_h)[2 * i]     = a;
    ((__half2*)g_fv_h)[2 * i + 1] = b;
}

// transpose [K,N] fp32 -> [N,K] fp16
__global__ void transpose_conv_kernel(const float* __restrict__ in,
                                      f16* __restrict__ oh,
                                      int K, int N) {
    __shared__ float t[32][33];
    int n0 = blockIdx.x * 32, k0 = blockIdx.y * 32;
    int tx = threadIdx.x, ty = threadIdx.y;   // (32, 8)
#pragma unroll
    for (int i = 0; i < 32; i += 8)
        t[ty + i][tx] = in[(size_t)(k0 + ty + i) * N + n0 + tx];
    __syncthreads();
#pragma unroll
    for (int i = 0; i < 32; i += 8) {
        float v = t[tx][ty + i];
        oh[(size_t)(n0 + ty + i) * K + k0 + tx] = __float2half_rn(v);
    }
}

// hs = hidden @ W_h + b_h  (fp32, tiny)
__global__ void hs_kernel(const float* __restrict__ hidden,
                          const float* __restrict__ Wh,
                          const float* __restrict__ bh) {
    int idx = blockIdx.x * blockDim.x + threadIdx.x;
    int b = idx >> 9;
    int i = idx & 511;
    const float* h = hidden + b * II;
    float acc = bh[i];
#pragma unroll 4
    for (int j = 0; j < II; ++j)
        acc = fmaf(h[j], Wh[j * II + i], acc);
    g_hs[idx] = acc;
}

// ---------------- tensor-core (mma.sync) GEMM ----------------
// C = A@B^T; A [M,K0] fp16 row-major, B [N,K0] fp16 K-major. Single pass.
// Tile 128x128, BK=64, 8 warps (64x32), 3-stage cp.async pipeline.
// Smem row: 128B (64 f16), swizzle byteoff = row*128 + (cb ^ ((row&7)<<4)).
// Stage s buffer at sbase + s*32768 (A) / +16384 (B); 3 stages = 96KB.

__device__ __forceinline__ void load_tile_async(uint32_t dst, const f16* src,
                                                int ldk, int tid) {
#pragma unroll
    for (int i = 0; i < 4; ++i) {
        int chunk = i * 256 + tid;
        int r = chunk >> 3, c16 = chunk & 7;
        const char* g = (const char*)src + (size_t)r * ldk * 2 + c16 * 16;
        uint32_t s = dst + r * 128 + ((c16 * 16) ^ ((r & 7) << 4));
        cp_async16(s, g);
    }
}

template <int EPI>
__global__ __launch_bounds__(256, 2)
void mma_gemm(const f16* __restrict__ Ah, const f16* __restrict__ Bh,
              const float* __restrict__ bias,
              float* __restrict__ Cf, f16* __restrict__ Ch,
              int N, int K0) {
    extern __shared__ char smem[];
    uint32_t sbase = smem_u32(smem);
    int tid = threadIdx.x, lane = tid & 31, wid = tid >> 5;
    int warp_m = wid >> 2, warp_n = wid & 3;
    int row0 = blockIdx.y * 128, col0 = blockIdx.x * 128;

    float c[4][4][4];
#pragma unroll
    for (int mi = 0; mi < 4; ++mi)
#pragma unroll
        for (int ni = 0; ni < 4; ++ni)
#pragma unroll
            for (int f = 0; f < 4; ++f) c[mi][ni][f] = 0.f;

    int nch = K0 / 64;

    auto issue = [&](int cc) {
        uint32_t buf = sbase + (uint32_t)(cc % 3) * 32768;
        int kk = cc * 64;
        load_tile_async(buf, Ah + (size_t)row0 * K0 + kk, K0, tid);
        load_tile_async(buf + 16384, Bh + (size_t)col0 * K0 + kk, K0, tid);
        cp_commit();
    };

    issue(0);
    if (nch > 1) issue(1);
    if (nch > 2) issue(2);

    int la15 = lane & 15, la7 = lane & 7;
    int a_cbsel = (lane >> 4) * 16;
    int b_cbsel = ((lane >> 3) & 1) * 16;
    int b_rowsel = (lane >> 4) * 8;

    for (int cc = 0; cc < nch; ++cc) {
        // chunks issued so far: through min(nch-1, cc+2).
        if (cc + 3 <= nch) cp_wait2();   // 3 pending -> oldest (cc) complete
        else               cp_wait0();   // tail: drain everything
        __syncthreads();

        uint32_t sA = sbase + (uint32_t)(cc % 3) * 32768;
        uint32_t sB = sA + 16384;
#pragma unroll
        for (int ks = 0; ks < 4; ++ks) {
            uint32_t a[4][4];
#pragma unroll
            for (int mi = 0; mi < 4; ++mi) {
                int row = warp_m * 64 + mi * 16 + la15;
                uint32_t cb = ks * 32 + a_cbsel;
                ldsm4(a[mi][0], a[mi][1], a[mi][2], a[mi][3],
                      sA + row * 128 + (cb ^ ((row & 7) << 4)));
            }
            uint32_t b[4][2];
#pragma unroll
            for (int nb = 0; nb < 2; ++nb) {
                int row = warp_n * 32 + nb * 16 + la7 + b_rowsel;
                uint32_t cb = ks * 32 + b_cbsel;
                ldsm4(b[2 * nb][0], b[2 * nb][1], b[2 * nb + 1][0], b[2 * nb + 1][1],
                      sB + row * 128 + (cb ^ ((row & 7) << 4)));
            }
#pragma unroll
            for (int mi = 0; mi < 4; ++mi)
#pragma unroll
                for (int ni = 0; ni < 4; ++ni)
                    mma16816(c[mi][ni], a[mi], b[ni]);
        }
        __syncthreads();   // all warps done with buffer cc%3
        if (cc + 3 < nch) issue(cc + 3);
    }

    // ---------------- epilogue ----------------
    int g = lane >> 2, tg = lane & 3;
#pragma unroll
    for (int mi = 0; mi < 4; ++mi) {
#pragma unroll
        for (int half = 0; half < 2; ++half) {
            int row = row0 + warp_m * 64 + mi * 16 + g + half * 8;
            const float* hsrow = (EPI == 0) ? (g_hs + (size_t)(row / LL) * II) : nullptr;
#pragma unroll
            for (int ni = 0; ni < 4; ++ni) {
                int col = col0 + warp_n * 32 + ni * 8 + tg * 2;
                float v0 = c[mi][ni][2 * half + 0];
                float v1 = c[mi][ni][2 * half + 1];
                v0 += bias[col];
                v1 += bias[col + 1];
                if (EPI == 0) {
                    v0 += hsrow[col];
                    v1 += hsrow[col + 1];
                    *(__half2*)(Ch + (size_t)row * N + col) = __floats2half2_rn(v0, v1);
                } else {
                    *(float2*)(Cf + (size_t)row * N + col) = make_float2(v0, v1);
                }
            }
        }
    }
}

// ---------------- softmax + z (float4, 4 lanes/thread) ----------------
__global__ void softmax_z_kernel(const float* __restrict__ fv,
                                 float* __restrict__ out) {
    int idx = blockIdx.x * blockDim.x + threadIdx.x;   // 0..BB*DD/4
    int b = idx / (DD / 4);
    int dq = (idx % (DD / 4));
    float4* e       = (float4*)(out + BB * DD + (size_t)b * LL * DD) + dq;
    const float4* f = (const float4*)(fv + (size_t)b * LL * DD) + dq;
    const int str = DD / 4;

    float4 m = make_float4(-INFINITY, -INFINITY, -INFINITY, -INFINITY);
    float4 s = make_float4(0.f, 0.f, 0.f, 0.f);
    for (int l = 0; l < LL; ++l) {
        float4 v = e[(size_t)l * str];
        if (v.x > m.x) { s.x *= __expf(m.x - v.x); m.x = v.x; }
        s.x += __expf(v.x - m.x);
        if (v.y > m.y) { s.y *= __expf(m.y - v.y); m.y = v.y; }
        s.y += __expf(v.y - m.y);
        if (v.z > m.z) { s.z *= __expf(m.z - v.z); m.z = v.z; }
        s.z += __expf(v.z - m.z);
        if (v.w > m.w) { s.w *= __expf(m.w - v.w); m.w = v.w; }
        s.w += __expf(v.w - m.w);
    }
    float4 inv = make_float4(1.f / s.x, 1.f / s.y, 1.f / s.z, 1.f / s.w);
    float4 z = make_float4(0.f, 0.f, 0.f, 0.f);
    for (int l = 0; l < LL; ++l) {
        size_t off = (size_t)l * str;
        float4 v = e[off];
        float4 fw = f[off];
        float4 p;
        p.x = __expf(v.x - m.x) * inv.x;
        p.y = __expf(v.y - m.y) * inv.y;
        p.z = __expf(v.z - m.z) * inv.z;
        p.w = __expf(v.w - m.w) * inv.w;
        e[off] = p;
        z.x = fmaf(p.x, fw.x, z.x);
        z.y = fmaf(p.y, fw.y, z.y);
        z.z = fmaf(p.z, fw.z, z.z);
        z.w = fmaf(p.w, fw.w, z.w);
    }
    ((float4*)out)[idx] = z;
}

// ---------------- launch ----------------
#define GEMM_SMEM 98304   // 3 stages x 32KB

extern "C" void kernel_launch(void* const* d_in, const int* in_sizes, int n_in,
                              void* d_out, int out_size) {
    const float* fv     = (const float*)d_in[0];
    const float* hidden = (const float*)d_in[1];
    const float* Wf     = (const float*)d_in[2];
    const float* bf     = (const float*)d_in[3];
    const float* Wh     = (const float*)d_in[4];
    const float* bh     = (const float*)d_in[5];
    const float* Wa     = (const float*)d_in[6];
    const float* ba     = (const float*)d_in[7];
    float* out = (float*)d_out;

    cudaFuncSetAttribute(mma_gemm<0>, cudaFuncAttributeMaxDynamicSharedMemorySize, GEMM_SMEM);
    cudaFuncSetAttribute(mma_gemm<1>, cudaFuncAttributeMaxDynamicSharedMemorySize, GEMM_SMEM);

    void* p;
    cudaGetSymbolAddress(&p, g_fv_h);    f16* fv_h  = (f16*)p;
    cudaGetSymbolAddress(&p, g_fvs_h);   f16* fvs_h = (f16*)p;
    cudaGetSymbolAddress(&p, g_WfT_h);   f16* WfT_h = (f16*)p;
    cudaGetSymbolAddress(&p, g_WaT_h);   f16* WaT_h = (f16*)p;

    // input conversions (independent)
    conv_fv_kernel<<<(size_t)MM * DD / 4 / 256, 256>>>(fv);
    hs_kernel<<<BB * II / 256, 256>>>(hidden, Wh, bh);
    transpose_conv_kernel<<<dim3(II / 32, DD / 32), dim3(32, 8)>>>(Wf, WfT_h, DD, II);
    transpose_conv_kernel<<<dim3(DD / 32, II / 32), dim3(32, 8)>>>(Wa, WaT_h, II, DD);

    // gemm1: fvs = fv @ Wf + bf + hs   (M=12544, N=512, K0=2048) -> fp16
    mma_gemm<0><<<dim3(II / 128, MM / 128), 256, GEMM_SMEM>>>(
        fv_h, WfT_h, bf, nullptr, fvs_h, II, DD);

    // gemm2: e = fvs @ Wa + ba   (M=12544, N=2048, K0=512) -> fp32 into out
    float* e = out + BB * DD;
    mma_gemm<1><<<dim3(DD / 128, MM / 128), 256, GEMM_SMEM>>>(
        fvs_h, WaT_h, ba, e, nullptr, DD, II);

    // softmax over L (in place) + z
    softmax_z_kernel<<<BB * DD / 4 / 256, 256>>>(fv, out);
}

// round 11
// speedup vs baseline: 1.2647x; 1.2647x over previous
#include <cuda_runtime.h>
#include <cuda_fp16.h>
#include <stdint.h>
#include <math.h>

#define BB 64
#define LL 196
#define DD 2048
#define II 512
#define MM (BB * LL)   // 12544

typedef __half f16;

// ---------------- device scratch (allocation-free) ----------------
__device__ f16 g_fv_h[(size_t)MM * DD];
__device__ f16 g_fvs_h[(size_t)MM * II];
__device__ f16 g_WfT_h[(size_t)II * DD];   // [I, D] K-major
__device__ f16 g_WaT_h[(size_t)DD * II];   // [D, I] K-major
__device__ float g_hs[BB * II];

// ---------------- helpers ----------------
__device__ __forceinline__ uint32_t smem_u32(const void* p) {
    uint32_t a;
    asm("{ .reg .u64 t; cvta.to.shared.u64 t, %1; cvt.u32.u64 %0, t; }"
        : "=r"(a) : "l"(p));
    return a;
}
__device__ __forceinline__ void cp_async16(uint32_t s, const void* g) {
    asm volatile("cp.async.cg.shared.global [%0], [%1], 16;" :: "r"(s), "l"(g));
}
__device__ __forceinline__ void cp_commit() {
    asm volatile("cp.async.commit_group;" ::: "memory");
}
__device__ __forceinline__ void cp_wait1() {
    asm volatile("cp.async.wait_group 1;" ::: "memory");
}
__device__ __forceinline__ void cp_wait0() {
    asm volatile("cp.async.wait_group 0;" ::: "memory");
}
__device__ __forceinline__ void ldsm4(uint32_t& r0, uint32_t& r1, uint32_t& r2,
                                      uint32_t& r3, uint32_t addr) {
    asm volatile("ldmatrix.sync.aligned.m8n8.x4.shared.b16 {%0,%1,%2,%3}, [%4];"
                 : "=r"(r0), "=r"(r1), "=r"(r2), "=r"(r3) : "r"(addr));
}
__device__ __forceinline__ void mma16816(float* c, const uint32_t* a,
                                         const uint32_t* b) {
    asm volatile(
        "mma.sync.aligned.m16n8k16.row.col.f32.f16.f16.f32 "
        "{%0,%1,%2,%3}, {%4,%5,%6,%7}, {%8,%9}, {%0,%1,%2,%3};"
        : "+f"(c[0]), "+f"(c[1]), "+f"(c[2]), "+f"(c[3])
        : "r"(a[0]), "r"(a[1]), "r"(a[2]), "r"(a[3]), "r"(b[0]), "r"(b[1]));
}

// ---------------- conversion kernels ----------------
// fv -> fp16
__global__ void conv_fv_kernel(const float* __restrict__ in) {
    size_t i = (size_t)blockIdx.x * blockDim.x + threadIdx.x;   // MM*DD/4
    float4 v = ((const float4*)in)[i];
    __half2 a = __floats2half2_rn(v.x, v.y);
    __half2 b = __floats2half2_rn(v.z, v.w);
    ((__half2*)g_fv_h)[2 * i]     = a;
    ((__half2*)g_fv_h)[2 * i + 1] = b;
}

// transpose [K,N] fp32 -> [N,K] fp16
__global__ void transpose_conv_kernel(const float* __restrict__ in,
                                      f16* __restrict__ oh,
                                      int K, int N) {
    __shared__ float t[32][33];
    int n0 = blockIdx.x * 32, k0 = blockIdx.y * 32;
    int tx = threadIdx.x, ty = threadIdx.y;   // (32, 8)
#pragma unroll
    for (int i = 0; i < 32; i += 8)
        t[ty + i][tx] = in[(size_t)(k0 + ty + i) * N + n0 + tx];
    __syncthreads();
#pragma unroll
    for (int i = 0; i < 32; i += 8) {
        float v = t[tx][ty + i];
        oh[(size_t)(n0 + ty + i) * K + k0 + tx] = __float2half_rn(v);
    }
}

// hs = hidden @ W_h + b_h  (fp32, tiny)
__global__ void hs_kernel(const float* __restrict__ hidden,
                          const float* __restrict__ Wh,
                          const float* __restrict__ bh) {
    int idx = blockIdx.x * blockDim.x + threadIdx.x;
    int b = idx >> 9;
    int i = idx & 511;
    const float* h = hidden + b * II;
    float acc = bh[i];
#pragma unroll 4
    for (int j = 0; j < II; ++j)
        acc = fmaf(h[j], Wh[j * II + i], acc);
    g_hs[idx] = acc;
}

// ---------------- tensor-core (mma.sync) GEMM ----------------
// C = A@B^T; A [M,K0] fp16 row-major, B [N,K0] fp16 K-major. Single pass.
// Tile 128x128, BK=64, 8 warps (64x32), 2-stage cp.async double buffer.
// Smem row: 128B (64 f16), swizzle byteoff = row*128 + (cb ^ ((row&7)<<4)).

__device__ __forceinline__ void load_tile_async(uint32_t dst, const f16* src,
                                                int ldk, int tid) {
#pragma unroll
    for (int i = 0; i < 4; ++i) {
        int chunk = i * 256 + tid;
        int r = chunk >> 3, c16 = chunk & 7;
        const char* g = (const char*)src + (size_t)r * ldk * 2 + c16 * 16;
        uint32_t s = dst + r * 128 + ((c16 * 16) ^ ((r & 7) << 4));
        cp_async16(s, g);
    }
}

template <int EPI>
__global__ __launch_bounds__(256, 2)
void mma_gemm(const f16* __restrict__ Ah, const f16* __restrict__ Bh,
              const float* __restrict__ bias,
              float* __restrict__ Cf, f16* __restrict__ Ch,
              int N, int K0) {
    extern __shared__ char smem[];
    uint32_t sbase = smem_u32(smem);
    int tid = threadIdx.x, lane = tid & 31, wid = tid >> 5;
    int warp_m = wid >> 2, warp_n = wid & 3;
    int row0 = blockIdx.y * 128, col0 = blockIdx.x * 128;

    float c[4][4][4];
#pragma unroll
    for (int mi = 0; mi < 4; ++mi)
#pragma unroll
        for (int ni = 0; ni < 4; ++ni)
#pragma unroll
            for (int f = 0; f < 4; ++f) c[mi][ni][f] = 0.f;

    int nch = K0 / 64;

    auto issue = [&](int cc) {
        int buf = cc & 1;
        int kk = cc * 64;
        load_tile_async(sbase + buf * 32768, Ah + (size_t)row0 * K0 + kk, K0, tid);
        load_tile_async(sbase + buf * 32768 + 16384, Bh + (size_t)col0 * K0 + kk, K0, tid);
        cp_commit();
    };

    issue(0);

    int la15 = lane & 15, la7 = lane & 7;
    int a_cbsel = (lane >> 4) * 16;
    int b_cbsel = ((lane >> 3) & 1) * 16;
    int b_rowsel = (lane >> 4) * 8;

    for (int cc = 0; cc < nch; ++cc) {
        if (cc + 1 < nch) { issue(cc + 1); cp_wait1(); }
        else              { cp_wait0(); }
        __syncthreads();

        uint32_t sA = sbase + (cc & 1) * 32768;
        uint32_t sB = sA + 16384;
#pragma unroll
        for (int ks = 0; ks < 4; ++ks) {
            uint32_t a[4][4];
#pragma unroll
            for (int mi = 0; mi < 4; ++mi) {
                int row = warp_m * 64 + mi * 16 + la15;
                uint32_t cb = ks * 32 + a_cbsel;
                ldsm4(a[mi][0], a[mi][1], a[mi][2], a[mi][3],
                      sA + row * 128 + (cb ^ ((row & 7) << 4)));
            }
            uint32_t b[4][2];
#pragma unroll
            for (int nb = 0; nb < 2; ++nb) {
                int row = warp_n * 32 + nb * 16 + la7 + b_rowsel;
                uint32_t cb = ks * 32 + b_cbsel;
                ldsm4(b[2 * nb][0], b[2 * nb][1], b[2 * nb + 1][0], b[2 * nb + 1][1],
                      sB + row * 128 + (cb ^ ((row & 7) << 4)));
            }
#pragma unroll
            for (int mi = 0; mi < 4; ++mi)
#pragma unroll
                for (int ni = 0; ni < 4; ++ni)
                    mma16816(c[mi][ni], a[mi], b[ni]);
        }
        __syncthreads();
    }

    // ---------------- epilogue ----------------
    int g = lane >> 2, tg = lane & 3;
#pragma unroll
    for (int mi = 0; mi < 4; ++mi) {
#pragma unroll
        for (int half = 0; half < 2; ++half) {
            int row = row0 + warp_m * 64 + mi * 16 + g + half * 8;
            const float* hsrow = (EPI == 0) ? (g_hs + (size_t)(row / LL) * II) : nullptr;
#pragma unroll
            for (int ni = 0; ni < 4; ++ni) {
                int col = col0 + warp_n * 32 + ni * 8 + tg * 2;
                float v0 = c[mi][ni][2 * half + 0];
                float v1 = c[mi][ni][2 * half + 1];
                v0 += bias[col];
                v1 += bias[col + 1];
                if (EPI == 0) {
                    v0 += hsrow[col];
                    v1 += hsrow[col + 1];
                    *(__half2*)(Ch + (size_t)row * N + col) = __floats2half2_rn(v0, v1);
                } else {
                    *(float2*)(Cf + (size_t)row * N + col) = make_float2(v0, v1);
                }
            }
        }
    }
}

// ---------------- softmax + z ----------------
// float2 per thread, 128-thread blocks -> 512 CTAs (balanced over 148 SMs).
// z-pass reads fv from the fp16 copy (half the traffic; z-only error ~2^-12).
__global__ __launch_bounds__(128)
void softmax_z_kernel(float* __restrict__ out) {
    int idx = blockIdx.x * blockDim.x + threadIdx.x;   // 0..BB*DD/2
    int b = idx / (DD / 2);
    int dp = idx % (DD / 2);
    float2* e        = (float2*)(out + BB * DD + (size_t)b * LL * DD) + dp;
    const __half2* f = ((const __half2*)g_fv_h) + (size_t)b * LL * (DD / 2) + dp;
    const int str = DD / 2;

    float2 m = make_float2(-INFINITY, -INFINITY);
    float2 s = make_float2(0.f, 0.f);
    for (int l = 0; l < LL; ++l) {
        float2 v = e[(size_t)l * str];
        if (v.x > m.x) { s.x *= __expf(m.x - v.x); m.x = v.x; }
        s.x += __expf(v.x - m.x);
        if (v.y > m.y) { s.y *= __expf(m.y - v.y); m.y = v.y; }
        s.y += __expf(v.y - m.y);
    }
    float2 inv = make_float2(1.f / s.x, 1.f / s.y);
    float2 z = make_float2(0.f, 0.f);
    for (int l = 0; l < LL; ++l) {
        size_t off = (size_t)l * str;
        float2 v = e[off];
        float2 fw = __half22float2(f[off]);
        float2 p;
        p.x = __expf(v.x - m.x) * inv.x;
        p.y = __expf(v.y - m.y) * inv.y;
        e[off] = p;
        z.x = fmaf(p.x, fw.x, z.x);
        z.y = fmaf(p.y, fw.y, z.y);
    }
    ((float2*)out)[idx] = z;
}

// ---------------- launch ----------------
#define GEMM_SMEM 65536

extern "C" void kernel_launch(void* const* d_in, const int* in_sizes, int n_in,
                              void* d_out, int out_size) {
    const float* fv     = (const float*)d_in[0];
    const float* hidden = (const float*)d_in[1];
    const float* Wf     = (const float*)d_in[2];
    const float* bf     = (const float*)d_in[3];
    const float* Wh     = (const float*)d_in[4];
    const float* bh     = (const float*)d_in[5];
    const float* Wa     = (const float*)d_in[6];
    const float* ba     = (const float*)d_in[7];
    float* out = (float*)d_out;

    cudaFuncSetAttribute(mma_gemm<0>, cudaFuncAttributeMaxDynamicSharedMemorySize, GEMM_SMEM);
    cudaFuncSetAttribute(mma_gemm<1>, cudaFuncAttributeMaxDynamicSharedMemorySize, GEMM_SMEM);

    void* p;
    cudaGetSymbolAddress(&p, g_fv_h);    f16* fv_h  = (f16*)p;
    cudaGetSymbolAddress(&p, g_fvs_h);   f16* fvs_h = (f16*)p;
    cudaGetSymbolAddress(&p, g_WfT_h);   f16* WfT_h = (f16*)p;
    cudaGetSymbolAddress(&p, g_WaT_h);   f16* WaT_h = (f16*)p;

    // input conversions (independent)
    conv_fv_kernel<<<(size_t)MM * DD / 4 / 256, 256>>>(fv);
    hs_kernel<<<BB * II / 256, 256>>>(hidden, Wh, bh);
    transpose_conv_kernel<<<dim3(II / 32, DD / 32), dim3(32, 8)>>>(Wf, WfT_h, DD, II);
    transpose_conv_kernel<<<dim3(DD / 32, II / 32), dim3(32, 8)>>>(Wa, WaT_h, II, DD);

    // gemm1: fvs = fv @ Wf + bf + hs   (M=12544, N=512, K0=2048) -> fp16
    mma_gemm<0><<<dim3(II / 128, MM / 128), 256, GEMM_SMEM>>>(
        fv_h, WfT_h, bf, nullptr, fvs_h, II, DD);

    // gemm2: e = fvs @ Wa + ba   (M=12544, N=2048, K0=512) -> fp32 into out
    float* e = out + BB * DD;
    mma_gemm<1><<<dim3(DD / 128, MM / 128), 256, GEMM_SMEM>>>(
        fvs_h, WaT_h, ba, e, nullptr, DD, II);

    // softmax over L (in place) + z
    softmax_z_kernel<<<BB * DD / 2 / 128, 128>>>(out);
}